// round 1
// baseline (speedup 1.0000x reference)
#include <cuda_runtime.h>
#include <cstdint>

#define NMAX 20000
#define EMAX 320000
#define F0 67
#define NC 16
#define MID 32

__device__ __constant__ float kY0 = 0.28209479177387814f;
#define C1F 0.4886025119029199f
#define Y0F 0.28209479177387814f

// ---------------- scratch (no allocations allowed) ----------------
__device__ float g_h0[NMAX * NC];
__device__ float g_h1[NMAX * NC];
__device__ int   g_deg[NMAX];
__device__ float g_invd[NMAX];
__device__ float g_hasin[NMAX];
__device__ float g_acc0a[NMAX * NC];
__device__ float g_acc0b[NMAX * NC];
__device__ float g_acc1[NMAX * NC * 3];

// ---------------- node embedding ----------------
__global__ void embed_kernel(const float* __restrict__ nf,
                             const float* __restrict__ W1, const float* __restrict__ b1,
                             const float* __restrict__ W2, const float* __restrict__ b2,
                             float* __restrict__ h0, int N) {
    __shared__ float x[F0], z[F0];
    int n = blockIdx.x;
    if (n >= N) return;
    int t = threadIdx.x;
    if (t < F0) x[t] = nf[n * F0 + t];
    __syncthreads();
    if (t < F0) {
        float a = b1[t];
#pragma unroll 1
        for (int k = 0; k < F0; ++k) a = fmaf(x[k], W1[k * F0 + t], a);
        z[t] = a > 0.f ? a : expm1f(a);
    }
    __syncthreads();
    if (t < NC) {
        float a = b2[t];
#pragma unroll 1
        for (int k = 0; k < F0; ++k) a = fmaf(z[k], W2[k * NC + t], a);
        h0[n * NC + t] = a;
    }
}

// ---------------- degree ----------------
__global__ void deg_kernel(const int* __restrict__ dst, int E, int* __restrict__ deg) {
    for (int i = blockIdx.x * blockDim.x + threadIdx.x; i < E; i += gridDim.x * blockDim.x)
        atomicAdd(&deg[dst[i]], 1);
}

__global__ void invdeg_kernel(const int* __restrict__ deg, int N,
                              float* __restrict__ invd, float* __restrict__ hasin) {
    for (int n = blockIdx.x * blockDim.x + threadIdx.x; n < N; n += gridDim.x * blockDim.x) {
        int d = deg[n];
        invd[n]  = d > 0 ? 1.0f / (float)d : 0.0f;
        hasin[n] = d > 0 ? 1.0f : 0.0f;
    }
}

// ---------------- node update: h_out = acc0*invd + hasin*(h_prev @ Wself^T) ----------------
__global__ void node_update_kernel(const float* __restrict__ acc0,
                                   const float* __restrict__ invd,
                                   const float* __restrict__ hasin,
                                   const float* __restrict__ hprev,
                                   const float* __restrict__ Wself, // [16,16], row o
                                   float* __restrict__ hout, int N) {
    int idx = blockIdx.x * blockDim.x + threadIdx.x;
    if (idx >= N * NC) return;
    int n = idx >> 4, o = idx & 15;
    const float* hr = &hprev[n * NC];
    const float* wr = &Wself[o * NC];
    float t = 0.f;
#pragma unroll
    for (int j = 0; j < NC; ++j) t = fmaf(hr[j], wr[j], t);
    hout[idx] = acc0[idx] * invd[n] + hasin[n] * t;
}

// ---------------- out1 finalize ----------------
__global__ void out1_kernel(const float* __restrict__ acc1, const float* __restrict__ invd,
                            float* __restrict__ out, int N) {
    int idx = blockIdx.x * blockDim.x + threadIdx.x;
    if (idx >= N * NC * 3) return;
    out[idx] = acc1[idx] * invd[idx / (NC * 3)];
}

// ---------------- fused edge kernel ----------------
// Phase A: warp-per-edge radial MLP (3 -> 32 -> LN -> relu -> 32 -> LN -> relu), H2 to smem.
// Phase B: register-tiled [64 x 32] @ [32 x 256] GEMM fused with per-edge contraction
//          against s = h_prev[src] and atomic scatter to dst accumulators.
struct EdgeSmem {
    float W3[2][MID * 256];     // 64 KB
    float W2[2][MID * MID];     // 8 KB
    float W1[2][3 * MID];
    float b1[2][MID], g1[2][MID], bb1[2][MID];
    float b2[2][MID], g2[2][MID], bb2[2][MID];
    float b3[2][256];
    float H2[2][64 * 33];       // pad 33 to dodge bank conflicts
    float S[64 * NC];
    float Y1[64][3];
    int   dstl[64];
};

__device__ __forceinline__ float warp_sum(float v) {
#pragma unroll
    for (int o = 16; o; o >>= 1) v += __shfl_xor_sync(0xffffffffu, v, o);
    return v;
}

__device__ __forceinline__ float ln_relu(float h, float g, float b) {
    float mu = warp_sum(h) * (1.0f / 32.0f);
    float c  = h - mu;
    float var = warp_sum(c * c) * (1.0f / 32.0f);
    float t = c * rsqrtf(var + 1e-5f);
    return fmaxf(fmaf(t, g, b), 0.0f);
}

template <int NNETS, bool DO_MSG1>
__global__ void __launch_bounds__(256, 2)
edge_kernel(const float* __restrict__ pos, const float* __restrict__ edge_w,
            const int* __restrict__ src, const int* __restrict__ dst,
            const float* __restrict__ hprev,
            const float* __restrict__ rW1, const float* __restrict__ rb1,
            const float* __restrict__ ln1g, const float* __restrict__ ln1b,
            const float* __restrict__ rW2, const float* __restrict__ rb2,
            const float* __restrict__ ln2g, const float* __restrict__ ln2b,
            const float* __restrict__ rW3, const float* __restrict__ rb3,
            float* __restrict__ acc0, float* __restrict__ acc1,
            int E, int netbase) {
    extern __shared__ __align__(16) float smem_raw[];
    EdgeSmem& sm = *reinterpret_cast<EdgeSmem*>(smem_raw);

    const int tid = threadIdx.x;
    const int lane = tid & 31, w = tid >> 5;
    const unsigned FULL = 0xffffffffu;

    // load weights for the nets this layer uses
#pragma unroll
    for (int nl = 0; nl < NNETS; ++nl) {
        int gi = netbase + nl;
        for (int x = tid; x < MID * 256; x += 256) sm.W3[nl][x] = rW3[gi * MID * 256 + x];
        for (int x = tid; x < MID * MID; x += 256) sm.W2[nl][x] = rW2[gi * MID * MID + x];
        if (tid < 3 * MID) sm.W1[nl][tid] = rW1[gi * 3 * MID + tid];
        if (tid < MID) {
            sm.b1[nl][tid]  = rb1[gi * MID + tid];
            sm.g1[nl][tid]  = ln1g[gi * MID + tid];
            sm.bb1[nl][tid] = ln1b[gi * MID + tid];
            sm.b2[nl][tid]  = rb2[gi * MID + tid];
            sm.g2[nl][tid]  = ln2g[gi * MID + tid];
            sm.bb2[nl][tid] = ln2b[gi * MID + tid];
        }
        if (tid < 256) sm.b3[nl][tid] = rb3[gi * 256 + tid];
    }
    __syncthreads();

    const int ntiles = (E + 63) >> 6;
    for (int tile = blockIdx.x; tile < ntiles; tile += gridDim.x) {
        const int base = tile << 6;

        // ---------- phase A ----------
        for (int jj = 0; jj < 8; ++jj) {
            int le = (w << 3) + jj;
            int ge = base + le;
            if (ge < E) {
                int sn = src[ge], dn = dst[ge];
                if (lane == 0) sm.dstl[le] = dn;
                if (lane < NC) sm.S[le * NC + lane] = hprev[sn * NC + lane];
                float dc = 0.f;
                if (lane < 3) dc = pos[dn * 3 + lane] - pos[sn * 3 + lane];
                float dx = __shfl_sync(FULL, dc, 0);
                float dy = __shfl_sync(FULL, dc, 1);
                float dz = __shfl_sync(FULL, dc, 2);
                float r = sqrtf(dx * dx + dy * dy + dz * dz);
                if (DO_MSG1 && lane < 3) {
                    float rm = fmaxf(r, 1e-8f);
                    float comp = lane == 0 ? dy : (lane == 1 ? dz : dx);
                    sm.Y1[le][lane] = C1F * comp / rm;
                }
                const float2 ew = reinterpret_cast<const float2*>(edge_w)[ge];
                float f0 = ew.x, f1 = ew.y, f2 = r;
#pragma unroll
                for (int nl = 0; nl < NNETS; ++nl) {
                    int m = lane;
                    float h = sm.b1[nl][m];
                    h = fmaf(f0, sm.W1[nl][m], h);
                    h = fmaf(f1, sm.W1[nl][MID + m], h);
                    h = fmaf(f2, sm.W1[nl][2 * MID + m], h);
                    h = ln_relu(h, sm.g1[nl][m], sm.bb1[nl][m]);
                    float h2 = sm.b2[nl][m];
#pragma unroll
                    for (int k = 0; k < MID; ++k)
                        h2 = fmaf(__shfl_sync(FULL, h, k), sm.W2[nl][k * MID + m], h2);
                    h2 = ln_relu(h2, sm.g2[nl][m], sm.bb2[nl][m]);
                    sm.H2[nl][le * 33 + m] = h2;
                }
            }
        }
        __syncthreads();

        // ---------- phase B ----------
        const int o = tid & 15, eg = tid >> 4;
        const int e0 = eg << 2;
#pragma unroll
        for (int nl = 0; nl < NNETS; ++nl) {
            float acc[4][16];
#pragma unroll
            for (int j = 0; j < 4; ++j)
#pragma unroll
                for (int i = 0; i < 16; ++i) acc[j][i] = 0.f;

            const float* __restrict__ w3p = sm.W3[nl];
            const float* __restrict__ h2p = sm.H2[nl];
#pragma unroll 4
            for (int k = 0; k < MID; ++k) {
                const float4* wrow = reinterpret_cast<const float4*>(&w3p[k * 256 + o * 16]);
                float4 wa = wrow[0], wb = wrow[1], wc = wrow[2], wd = wrow[3];
                float hh[4];
#pragma unroll
                for (int j = 0; j < 4; ++j) hh[j] = h2p[(e0 + j) * 33 + k];
#pragma unroll
                for (int j = 0; j < 4; ++j) {
                    acc[j][0]  = fmaf(hh[j], wa.x, acc[j][0]);
                    acc[j][1]  = fmaf(hh[j], wa.y, acc[j][1]);
                    acc[j][2]  = fmaf(hh[j], wa.z, acc[j][2]);
                    acc[j][3]  = fmaf(hh[j], wa.w, acc[j][3]);
                    acc[j][4]  = fmaf(hh[j], wb.x, acc[j][4]);
                    acc[j][5]  = fmaf(hh[j], wb.y, acc[j][5]);
                    acc[j][6]  = fmaf(hh[j], wb.z, acc[j][6]);
                    acc[j][7]  = fmaf(hh[j], wb.w, acc[j][7]);
                    acc[j][8]  = fmaf(hh[j], wc.x, acc[j][8]);
                    acc[j][9]  = fmaf(hh[j], wc.y, acc[j][9]);
                    acc[j][10] = fmaf(hh[j], wc.z, acc[j][10]);
                    acc[j][11] = fmaf(hh[j], wc.w, acc[j][11]);
                    acc[j][12] = fmaf(hh[j], wd.x, acc[j][12]);
                    acc[j][13] = fmaf(hh[j], wd.y, acc[j][13]);
                    acc[j][14] = fmaf(hh[j], wd.z, acc[j][14]);
                    acc[j][15] = fmaf(hh[j], wd.w, acc[j][15]);
                }
            }
#pragma unroll
            for (int j = 0; j < 4; ++j) {
                int le = e0 + j;
                int ge = base + le;
                if (ge < E) {
                    const float* sv = &sm.S[le * NC];
                    float t = 0.f;
#pragma unroll
                    for (int i = 0; i < 16; ++i)
                        t = fmaf(acc[j][i] + sm.b3[nl][o * 16 + i], sv[i], t);
                    int dn = sm.dstl[le];
                    if (nl == 0) {
                        atomicAdd(&acc0[dn * NC + o], Y0F * t);
                    } else if (DO_MSG1) {
                        float y0 = sm.Y1[le][0], y1 = sm.Y1[le][1], y2 = sm.Y1[le][2];
                        atomicAdd(&acc1[dn * NC * 3 + o * 3 + 0], t * y0);
                        atomicAdd(&acc1[dn * NC * 3 + o * 3 + 1], t * y1);
                        atomicAdd(&acc1[dn * NC * 3 + o * 3 + 2], t * y2);
                    }
                }
            }
        }
        __syncthreads();
    }
}

// ---------------- launch ----------------
extern "C" void kernel_launch(void* const* d_in, const int* in_sizes, int n_in,
                              void* d_out, int out_size) {
    const float* node_feats = (const float*)d_in[0];
    const float* pos        = (const float*)d_in[1];
    const float* edge_w     = (const float*)d_in[2];
    const float* lin1_W     = (const float*)d_in[3];
    const float* lin1_b     = (const float*)d_in[4];
    const float* lin2_W     = (const float*)d_in[5];
    const float* lin2_b     = (const float*)d_in[6];
    const float* rW1        = (const float*)d_in[7];
    const float* rb1        = (const float*)d_in[8];
    const float* ln1g       = (const float*)d_in[9];
    const float* ln1b       = (const float*)d_in[10];
    const float* rW2        = (const float*)d_in[11];
    const float* rb2        = (const float*)d_in[12];
    const float* ln2g       = (const float*)d_in[13];
    const float* ln2b       = (const float*)d_in[14];
    const float* rW3        = (const float*)d_in[15];
    const float* rb3        = (const float*)d_in[16];
    const float* Wself      = (const float*)d_in[17];
    const int*   src        = (const int*)d_in[18];
    const int*   dst        = (const int*)d_in[19];

    const int N = in_sizes[0] / F0;
    const int E = in_sizes[18];

    float *h0, *h1, *invd, *hasin, *acc0a, *acc0b, *acc1;
    int* deg;
    cudaGetSymbolAddress((void**)&h0, g_h0);
    cudaGetSymbolAddress((void**)&h1, g_h1);
    cudaGetSymbolAddress((void**)&deg, g_deg);
    cudaGetSymbolAddress((void**)&invd, g_invd);
    cudaGetSymbolAddress((void**)&hasin, g_hasin);
    cudaGetSymbolAddress((void**)&acc0a, g_acc0a);
    cudaGetSymbolAddress((void**)&acc0b, g_acc0b);
    cudaGetSymbolAddress((void**)&acc1, g_acc1);

    const size_t smemBytes = sizeof(EdgeSmem);
    cudaFuncSetAttribute(edge_kernel<1, false>, cudaFuncAttributeMaxDynamicSharedMemorySize, (int)smemBytes);
    cudaFuncSetAttribute(edge_kernel<2, true>,  cudaFuncAttributeMaxDynamicSharedMemorySize, (int)smemBytes);

    cudaMemsetAsync(deg,   0, (size_t)N * sizeof(int));
    cudaMemsetAsync(acc0a, 0, (size_t)N * NC * sizeof(float));
    cudaMemsetAsync(acc0b, 0, (size_t)N * NC * sizeof(float));
    cudaMemsetAsync(acc1,  0, (size_t)N * NC * 3 * sizeof(float));

    // node embedding
    embed_kernel<<<N, 96>>>(node_feats, lin1_W, lin1_b, lin2_W, lin2_b, h0, N);

    // degree
    deg_kernel<<<512, 256>>>(dst, E, deg);
    invdeg_kernel<<<(N + 255) / 256, 256>>>(deg, N, invd, hasin);

    const int ntiles = (E + 63) / 64;
    int eblocks = ntiles < 304 ? ntiles : 304;

    // layer 0: only radial net 0 (msg0); layer-0 msg1 is overwritten downstream -> skipped
    edge_kernel<1, false><<<eblocks, 256, smemBytes>>>(
        pos, edge_w, src, dst, h0,
        rW1, rb1, ln1g, ln1b, rW2, rb2, ln2g, ln2b, rW3, rb3,
        acc0a, acc1, E, 0);
    node_update_kernel<<<(N * NC + 255) / 256, 256>>>(acc0a, invd, hasin, h0, Wself + 0 * NC * NC, h1, N);

    // layer 1: radial nets 2 (msg0) and 3 (msg1)
    edge_kernel<2, true><<<eblocks, 256, smemBytes>>>(
        pos, edge_w, src, dst, h1,
        rW1, rb1, ln1g, ln1b, rW2, rb2, ln2g, ln2b, rW3, rb3,
        acc0b, acc1, E, 2);

    float* out = (float*)d_out;
    node_update_kernel<<<(N * NC + 255) / 256, 256>>>(acc0b, invd, hasin, h1, Wself + 1 * NC * NC, out, N);
    out1_kernel<<<(N * NC * 3 + 255) / 256, 256>>>(acc1, invd, out + (size_t)N * NC, N);
}

// round 2
// speedup vs baseline: 1.5280x; 1.5280x over previous
#include <cuda_runtime.h>
#include <cstdint>

#define NMAX 20000
#define EMAX 320000
#define F0 67
#define NC 16
#define MID 32

#define C1F 0.4886025119029199f
#define Y0F 0.28209479177387814f

// ---------------- scratch (no allocations allowed) ----------------
__device__ float g_h0[NMAX * NC];
__device__ float g_h1[NMAX * NC];
__device__ int   g_deg[NMAX];
__device__ float g_invd[NMAX];
__device__ float g_hasin[NMAX];
__device__ float g_acc0a[NMAX * NC];
__device__ float g_acc0b[NMAX * NC];
__device__ float g_acc1[NMAX * NC * 3];

// ---------------- node embedding ----------------
__global__ void embed_kernel(const float* __restrict__ nf,
                             const float* __restrict__ W1, const float* __restrict__ b1,
                             const float* __restrict__ W2, const float* __restrict__ b2,
                             float* __restrict__ h0, int N) {
    __shared__ float x[F0], z[F0];
    int n = blockIdx.x;
    if (n >= N) return;
    int t = threadIdx.x;
    if (t < F0) x[t] = nf[n * F0 + t];
    __syncthreads();
    if (t < F0) {
        float a = b1[t];
#pragma unroll 1
        for (int k = 0; k < F0; ++k) a = fmaf(x[k], W1[k * F0 + t], a);
        z[t] = a > 0.f ? a : expm1f(a);
    }
    __syncthreads();
    if (t < NC) {
        float a = b2[t];
#pragma unroll 1
        for (int k = 0; k < F0; ++k) a = fmaf(z[k], W2[k * NC + t], a);
        h0[n * NC + t] = a;
    }
}

// ---------------- degree ----------------
__global__ void deg_kernel(const int* __restrict__ dst, int E, int* __restrict__ deg) {
    for (int i = blockIdx.x * blockDim.x + threadIdx.x; i < E; i += gridDim.x * blockDim.x)
        atomicAdd(&deg[dst[i]], 1);
}

__global__ void invdeg_kernel(const int* __restrict__ deg, int N,
                              float* __restrict__ invd, float* __restrict__ hasin) {
    for (int n = blockIdx.x * blockDim.x + threadIdx.x; n < N; n += gridDim.x * blockDim.x) {
        int d = deg[n];
        invd[n]  = d > 0 ? 1.0f / (float)d : 0.0f;
        hasin[n] = d > 0 ? 1.0f : 0.0f;
    }
}

// ---------------- node update ----------------
__global__ void node_update_kernel(const float* __restrict__ acc0,
                                   const float* __restrict__ invd,
                                   const float* __restrict__ hasin,
                                   const float* __restrict__ hprev,
                                   const float* __restrict__ Wself,
                                   float* __restrict__ hout, int N) {
    int idx = blockIdx.x * blockDim.x + threadIdx.x;
    if (idx >= N * NC) return;
    int n = idx >> 4, o = idx & 15;
    const float* hr = &hprev[n * NC];
    const float* wr = &Wself[o * NC];
    float t = 0.f;
#pragma unroll
    for (int j = 0; j < NC; ++j) t = fmaf(hr[j], wr[j], t);
    hout[idx] = acc0[idx] * invd[n] + hasin[n] * t;
}

// ---------------- out1 finalize ----------------
__global__ void out1_kernel(const float* __restrict__ acc1, const float* __restrict__ invd,
                            float* __restrict__ out, int N) {
    int idx = blockIdx.x * blockDim.x + threadIdx.x;
    if (idx >= N * NC * 3) return;
    out[idx] = acc1[idx] * invd[idx / (NC * 3)];
}

// ---------------- fused edge kernel ----------------
struct EdgeSmem {
    float W3[2][MID * 256];     // 64 KB
    float W2[2][MID * MID];     // 8 KB
    float W1[2][3 * MID];
    float b1[2][MID], g1[2][MID], bb1[2][MID];
    float b2[2][MID], g2[2][MID], bb2[2][MID];
    float b3[2][256];
    float H2[2][64 * 33];       // pad 33 to dodge bank conflicts
    float S[64 * NC];           // 16B-aligned by construction
    float Y1[64][3];
    int   dstl[64];
};

__device__ __forceinline__ float warp_sum(float v) {
#pragma unroll
    for (int o = 16; o; o >>= 1) v += __shfl_xor_sync(0xffffffffu, v, o);
    return v;
}

__device__ __forceinline__ float ln_relu(float h, float g, float b) {
    float mu = warp_sum(h) * (1.0f / 32.0f);
    float c  = h - mu;
    float var = warp_sum(c * c) * (1.0f / 32.0f);
    float t = c * rsqrtf(var + 1e-5f);
    return fmaxf(fmaf(t, g, b), 0.0f);
}

__device__ __forceinline__ unsigned long long pack2(float x, float y) {
    unsigned long long r;
    asm("mov.b64 %0, {%1, %2};" : "=l"(r) : "f"(x), "f"(y));
    return r;
}
__device__ __forceinline__ unsigned long long dup2(float x) {
    unsigned long long r;
    asm("mov.b64 %0, {%1, %1};" : "=l"(r) : "f"(x));
    return r;
}
__device__ __forceinline__ void unpack2(unsigned long long p, float& x, float& y) {
    asm("mov.b64 {%0, %1}, %2;" : "=f"(x), "=f"(y) : "l"(p));
}
__device__ __forceinline__ void ffma2(unsigned long long& d, unsigned long long a, unsigned long long b) {
    asm("fma.rn.f32x2 %0, %1, %2, %0;" : "+l"(d) : "l"(a), "l"(b));
}

template <int NNETS, bool DO_MSG1>
__global__ void __launch_bounds__(256, 2)
edge_kernel(const float* __restrict__ pos, const float* __restrict__ edge_w,
            const int* __restrict__ src, const int* __restrict__ dst,
            const float* __restrict__ hprev,
            const float* __restrict__ rW1, const float* __restrict__ rb1,
            const float* __restrict__ ln1g, const float* __restrict__ ln1b,
            const float* __restrict__ rW2, const float* __restrict__ rb2,
            const float* __restrict__ ln2g, const float* __restrict__ ln2b,
            const float* __restrict__ rW3, const float* __restrict__ rb3,
            float* __restrict__ acc0, float* __restrict__ acc1,
            int E, int netbase) {
    extern __shared__ __align__(16) float smem_raw[];
    EdgeSmem& sm = *reinterpret_cast<EdgeSmem*>(smem_raw);

    const int tid = threadIdx.x;
    const int lane = tid & 31, w = tid >> 5;
    const unsigned FULL = 0xffffffffu;

    // load weights
#pragma unroll
    for (int nl = 0; nl < NNETS; ++nl) {
        int gi = netbase + nl;
        for (int x = tid; x < MID * 256; x += 256) sm.W3[nl][x] = rW3[gi * MID * 256 + x];
        for (int x = tid; x < MID * MID; x += 256) sm.W2[nl][x] = rW2[gi * MID * MID + x];
        if (tid < 3 * MID) sm.W1[nl][tid] = rW1[gi * 3 * MID + tid];
        if (tid < MID) {
            sm.b1[nl][tid]  = rb1[gi * MID + tid];
            sm.g1[nl][tid]  = ln1g[gi * MID + tid];
            sm.bb1[nl][tid] = ln1b[gi * MID + tid];
            sm.b2[nl][tid]  = rb2[gi * MID + tid];
            sm.g2[nl][tid]  = ln2g[gi * MID + tid];
            sm.bb2[nl][tid] = ln2b[gi * MID + tid];
        }
        if (tid < 256) sm.b3[nl][tid] = rb3[gi * 256 + tid];
    }
    __syncthreads();

    // phase-B mapping: c = output column group (4 consecutive cols), eg = edge group (16 edges)
    const int c  = tid & 63;
    const int e0 = (tid >> 6) << 4;
    const int o  = c >> 2;           // output row 0..15
    const int i0 = (c & 3) << 2;     // input-col offset 0,4,8,12

    const int ntiles = (E + 63) >> 6;
    for (int tile = blockIdx.x; tile < ntiles; tile += gridDim.x) {
        const int base = tile << 6;

        // ---------- phase A: radial MLP, warp-per-edge ----------
        for (int jj = 0; jj < 8; ++jj) {
            int le = (w << 3) + jj;
            int ge = base + le;
            if (ge < E) {
                int sn = src[ge], dn = dst[ge];
                if (lane == 0) sm.dstl[le] = dn;
                if (lane < NC) sm.S[le * NC + lane] = hprev[sn * NC + lane];
                float dc = 0.f;
                if (lane < 3) dc = pos[dn * 3 + lane] - pos[sn * 3 + lane];
                float dx = __shfl_sync(FULL, dc, 0);
                float dy = __shfl_sync(FULL, dc, 1);
                float dz = __shfl_sync(FULL, dc, 2);
                float r = sqrtf(dx * dx + dy * dy + dz * dz);
                if (DO_MSG1 && lane < 3) {
                    float rm = fmaxf(r, 1e-8f);
                    float comp = lane == 0 ? dy : (lane == 1 ? dz : dx);
                    sm.Y1[le][lane] = C1F * comp / rm;
                }
                const float2 ew = reinterpret_cast<const float2*>(edge_w)[ge];
                float f0 = ew.x, f1 = ew.y, f2 = r;
#pragma unroll
                for (int nl = 0; nl < NNETS; ++nl) {
                    int m = lane;
                    float h = sm.b1[nl][m];
                    h = fmaf(f0, sm.W1[nl][m], h);
                    h = fmaf(f1, sm.W1[nl][MID + m], h);
                    h = fmaf(f2, sm.W1[nl][2 * MID + m], h);
                    h = ln_relu(h, sm.g1[nl][m], sm.bb1[nl][m]);
                    float h2 = sm.b2[nl][m];
#pragma unroll
                    for (int k = 0; k < MID; ++k)
                        h2 = fmaf(__shfl_sync(FULL, h, k), sm.W2[nl][k * MID + m], h2);
                    h2 = ln_relu(h2, sm.g2[nl][m], sm.bb2[nl][m]);
                    sm.H2[nl][le * 33 + m] = h2;
                }
            }
        }
        __syncthreads();

        // ---------- phase B: [64x32] @ [32x256] GEMM with packed f32x2 FMA ----------
#pragma unroll
        for (int nl = 0; nl < NNETS; ++nl) {
            unsigned long long acc[16][2];
#pragma unroll
            for (int j = 0; j < 16; ++j) { acc[j][0] = 0ull; acc[j][1] = 0ull; }

            const float* __restrict__ w3p = sm.W3[nl] + c * 4;
            const float* __restrict__ h2p = sm.H2[nl] + e0 * 33;
#pragma unroll 4
            for (int k = 0; k < MID; ++k) {
                // lane-consecutive float4 -> conflict-free LDS.128
                float4 wv = *reinterpret_cast<const float4*>(&w3p[k * 256]);
                unsigned long long w01 = pack2(wv.x, wv.y);
                unsigned long long w23 = pack2(wv.z, wv.w);
#pragma unroll
                for (int j = 0; j < 16; ++j) {
                    // warp-uniform address -> broadcast LDS
                    unsigned long long hp = dup2(h2p[j * 33 + k]);
                    ffma2(acc[j][0], hp, w01);
                    ffma2(acc[j][1], hp, w23);
                }
            }

            // epilogue: contract with s, butterfly-reduce over the 4-lane column group
            const float4 b3v = *reinterpret_cast<const float4*>(&sm.b3[nl][c * 4]);
#pragma unroll
            for (int j = 0; j < 16; ++j) {
                int le = e0 + j;
                int ge = base + le;
                if (ge < E) {                 // warp-uniform guard
                    float a0, a1, a2, a3;
                    unpack2(acc[j][0], a0, a1);
                    unpack2(acc[j][1], a2, a3);
                    const float4 s4 = *reinterpret_cast<const float4*>(&sm.S[le * NC + i0]);
                    float t;
                    t = (a0 + b3v.x) * s4.x;
                    t = fmaf(a1 + b3v.y, s4.y, t);
                    t = fmaf(a2 + b3v.z, s4.z, t);
                    t = fmaf(a3 + b3v.w, s4.w, t);
                    t += __shfl_xor_sync(FULL, t, 1);
                    t += __shfl_xor_sync(FULL, t, 2);
                    if ((c & 3) == 0) {
                        int dn = sm.dstl[le];
                        if (nl == 0) {
                            atomicAdd(&acc0[dn * NC + o], Y0F * t);
                        } else if (DO_MSG1) {
                            float y0 = sm.Y1[le][0], y1 = sm.Y1[le][1], y2 = sm.Y1[le][2];
                            atomicAdd(&acc1[dn * NC * 3 + o * 3 + 0], t * y0);
                            atomicAdd(&acc1[dn * NC * 3 + o * 3 + 1], t * y1);
                            atomicAdd(&acc1[dn * NC * 3 + o * 3 + 2], t * y2);
                        }
                    }
                }
            }
        }
        __syncthreads();
    }
}

// ---------------- launch ----------------
extern "C" void kernel_launch(void* const* d_in, const int* in_sizes, int n_in,
                              void* d_out, int out_size) {
    const float* node_feats = (const float*)d_in[0];
    const float* pos        = (const float*)d_in[1];
    const float* edge_w     = (const float*)d_in[2];
    const float* lin1_W     = (const float*)d_in[3];
    const float* lin1_b     = (const float*)d_in[4];
    const float* lin2_W     = (const float*)d_in[5];
    const float* lin2_b     = (const float*)d_in[6];
    const float* rW1        = (const float*)d_in[7];
    const float* rb1        = (const float*)d_in[8];
    const float* ln1g       = (const float*)d_in[9];
    const float* ln1b       = (const float*)d_in[10];
    const float* rW2        = (const float*)d_in[11];
    const float* rb2        = (const float*)d_in[12];
    const float* ln2g       = (const float*)d_in[13];
    const float* ln2b       = (const float*)d_in[14];
    const float* rW3        = (const float*)d_in[15];
    const float* rb3        = (const float*)d_in[16];
    const float* Wself      = (const float*)d_in[17];
    const int*   src        = (const int*)d_in[18];
    const int*   dst        = (const int*)d_in[19];

    const int N = in_sizes[0] / F0;
    const int E = in_sizes[18];

    float *h0, *h1, *invd, *hasin, *acc0a, *acc0b, *acc1;
    int* deg;
    cudaGetSymbolAddress((void**)&h0, g_h0);
    cudaGetSymbolAddress((void**)&h1, g_h1);
    cudaGetSymbolAddress((void**)&deg, g_deg);
    cudaGetSymbolAddress((void**)&invd, g_invd);
    cudaGetSymbolAddress((void**)&hasin, g_hasin);
    cudaGetSymbolAddress((void**)&acc0a, g_acc0a);
    cudaGetSymbolAddress((void**)&acc0b, g_acc0b);
    cudaGetSymbolAddress((void**)&acc1, g_acc1);

    const size_t smemBytes = sizeof(EdgeSmem);
    cudaFuncSetAttribute(edge_kernel<1, false>, cudaFuncAttributeMaxDynamicSharedMemorySize, (int)smemBytes);
    cudaFuncSetAttribute(edge_kernel<2, true>,  cudaFuncAttributeMaxDynamicSharedMemorySize, (int)smemBytes);

    cudaMemsetAsync(deg,   0, (size_t)N * sizeof(int));
    cudaMemsetAsync(acc0a, 0, (size_t)N * NC * sizeof(float));
    cudaMemsetAsync(acc0b, 0, (size_t)N * NC * sizeof(float));
    cudaMemsetAsync(acc1,  0, (size_t)N * NC * 3 * sizeof(float));

    embed_kernel<<<N, 96>>>(node_feats, lin1_W, lin1_b, lin2_W, lin2_b, h0, N);
    deg_kernel<<<512, 256>>>(dst, E, deg);
    invdeg_kernel<<<(N + 255) / 256, 256>>>(deg, N, invd, hasin);

    const int ntiles = (E + 63) / 64;
    int eblocks = ntiles < 304 ? ntiles : 304;

    // layer 0: only radial net 0 (msg0); layer-0 msg1 is dead code in the reference
    edge_kernel<1, false><<<eblocks, 256, smemBytes>>>(
        pos, edge_w, src, dst, h0,
        rW1, rb1, ln1g, ln1b, rW2, rb2, ln2g, ln2b, rW3, rb3,
        acc0a, acc1, E, 0);
    node_update_kernel<<<(N * NC + 255) / 256, 256>>>(acc0a, invd, hasin, h0, Wself + 0 * NC * NC, h1, N);

    // layer 1: radial nets 2 (msg0) and 3 (msg1)
    edge_kernel<2, true><<<eblocks, 256, smemBytes>>>(
        pos, edge_w, src, dst, h1,
        rW1, rb1, ln1g, ln1b, rW2, rb2, ln2g, ln2b, rW3, rb3,
        acc0b, acc1, E, 2);

    float* out = (float*)d_out;
    node_update_kernel<<<(N * NC + 255) / 256, 256>>>(acc0b, invd, hasin, h1, Wself + 1 * NC * NC, out, N);
    out1_kernel<<<(N * NC * 3 + 255) / 256, 256>>>(acc1, invd, out + (size_t)N * NC, N);
}

// round 3
// speedup vs baseline: 2.1811x; 1.4274x over previous
#include <cuda_runtime.h>
#include <cstdint>

#define NMAX 20000
#define EMAX 320000
#define F0 67
#define NC 16
#define MID 32

#define C1F 0.4886025119029199f
#define Y0F 0.28209479177387814f

// ---------------- scratch ----------------
__device__ float g_h0[NMAX * NC];
__device__ float g_h1[NMAX * NC];
__device__ int   g_deg[NMAX];
__device__ float g_invd[NMAX];
__device__ float g_hasin[NMAX];
__device__ float g_acc0a[NMAX * NC];
__device__ float g_acc0b[NMAX * NC];
__device__ float g_acc1[NMAX * NC * 3];

// ---------------- node embedding: 8 nodes/block, weights cached in smem ----------------
#define EMB_NODES 8
__global__ void __launch_bounds__(256) embed_kernel(
        const float* __restrict__ nf,
        const float* __restrict__ W1, const float* __restrict__ b1,
        const float* __restrict__ W2, const float* __restrict__ b2,
        float* __restrict__ h0, int N) {
    __shared__ float W1s[F0 * F0];
    __shared__ float W2s[F0 * NC];
    __shared__ float b1s[F0];
    __shared__ float b2s[NC];
    __shared__ float xs[EMB_NODES * F0];
    __shared__ float zs[EMB_NODES * F0];
    const int tid = threadIdx.x;
    const int base = blockIdx.x * EMB_NODES;
    if (base >= N) return;
    const int nn = (N - base) < EMB_NODES ? (N - base) : EMB_NODES;

    for (int i = tid; i < F0 * F0; i += 256) W1s[i] = W1[i];
    for (int i = tid; i < F0 * NC; i += 256) W2s[i] = W2[i];
    if (tid < F0) b1s[tid] = b1[tid];
    if (tid < NC) b2s[tid] = b2[tid];
    for (int i = tid; i < nn * F0; i += 256) xs[i] = nf[base * F0 + i];
    __syncthreads();

    for (int oi = tid; oi < nn * F0; oi += 256) {
        int node = oi / F0, f = oi - node * F0;
        float a = b1s[f];
        const float* xr = &xs[node * F0];
#pragma unroll 1
        for (int k = 0; k < F0; ++k) a = fmaf(xr[k], W1s[k * F0 + f], a);
        zs[oi] = a > 0.f ? a : expm1f(a);
    }
    __syncthreads();

    for (int oi = tid; oi < nn * NC; oi += 256) {
        int node = oi >> 4, o = oi & 15;
        float a = b2s[o];
        const float* zr = &zs[node * F0];
#pragma unroll 1
        for (int k = 0; k < F0; ++k) a = fmaf(zr[k], W2s[k * NC + o], a);
        h0[base * NC + oi] = a;
    }
}

// ---------------- degree ----------------
__global__ void deg_kernel(const int* __restrict__ dst, int E, int* __restrict__ deg) {
    for (int i = blockIdx.x * blockDim.x + threadIdx.x; i < E; i += gridDim.x * blockDim.x)
        atomicAdd(&deg[dst[i]], 1);
}

__global__ void invdeg_kernel(const int* __restrict__ deg, int N,
                              float* __restrict__ invd, float* __restrict__ hasin) {
    for (int n = blockIdx.x * blockDim.x + threadIdx.x; n < N; n += gridDim.x * blockDim.x) {
        int d = deg[n];
        invd[n]  = d > 0 ? 1.0f / (float)d : 0.0f;
        hasin[n] = d > 0 ? 1.0f : 0.0f;
    }
}

// ---------------- node update ----------------
__global__ void node_update_kernel(const float* __restrict__ acc0,
                                   const float* __restrict__ invd,
                                   const float* __restrict__ hasin,
                                   const float* __restrict__ hprev,
                                   const float* __restrict__ Wself,
                                   float* __restrict__ hout, int N) {
    int idx = blockIdx.x * blockDim.x + threadIdx.x;
    if (idx >= N * NC) return;
    int n = idx >> 4, o = idx & 15;
    const float* hr = &hprev[n * NC];
    const float* wr = &Wself[o * NC];
    float t = 0.f;
#pragma unroll
    for (int j = 0; j < NC; ++j) t = fmaf(hr[j], wr[j], t);
    hout[idx] = acc0[idx] * invd[n] + hasin[n] * t;
}

// ---------------- out1 finalize ----------------
__global__ void out1_kernel(const float* __restrict__ acc1, const float* __restrict__ invd,
                            float* __restrict__ out, int N) {
    int idx = blockIdx.x * blockDim.x + threadIdx.x;
    if (idx >= N * NC * 3) return;
    out[idx] = acc1[idx] * invd[idx / (NC * 3)];
}

// ---------------- fused edge kernel (single radial net per launch) ----------------
struct EdgeSmem {
    float W3[MID * 256];      // 32 KB
    float W2[MID * MID];      // 4 KB
    float W1[3 * MID];
    float b1[MID], g1[MID], bb1[MID];
    float b2[MID], g2[MID], bb2[MID];
    float b3[256];
    float H2d[64 * 68];       // dup pairs {h,h} per k, row = 272 B (16B aligned)
    float S[64 * NC];
    float Y1[64][3];
    int   dstl[64];
};

__device__ __forceinline__ unsigned long long dup2(float x) {
    unsigned long long r;
    asm("mov.b64 %0, {%1, %1};" : "=l"(r) : "f"(x));
    return r;
}
__device__ __forceinline__ void unpack2(unsigned long long p, float& x, float& y) {
    asm("mov.b64 {%0, %1}, %2;" : "=f"(x), "=f"(y) : "l"(p));
}
__device__ __forceinline__ void ffma2(unsigned long long& d, unsigned long long a, unsigned long long b) {
    asm("fma.rn.f32x2 %0, %1, %2, %0;" : "+l"(d) : "l"(a), "l"(b));
}

template <bool DO_MSG1>
__global__ void __launch_bounds__(256, 3)
edge_kernel(const float* __restrict__ pos, const float* __restrict__ edge_w,
            const int* __restrict__ src, const int* __restrict__ dst,
            const float* __restrict__ hprev,
            const float* __restrict__ rW1, const float* __restrict__ rb1,
            const float* __restrict__ ln1g, const float* __restrict__ ln1b,
            const float* __restrict__ rW2, const float* __restrict__ rb2,
            const float* __restrict__ ln2g, const float* __restrict__ ln2b,
            const float* __restrict__ rW3, const float* __restrict__ rb3,
            float* __restrict__ accOut, int E) {
    extern __shared__ __align__(16) float smem_raw[];
    EdgeSmem& sm = *reinterpret_cast<EdgeSmem*>(smem_raw);

    const int tid = threadIdx.x;
    const int lane = tid & 31, w = tid >> 5;
    const unsigned FULL = 0xffffffffu;

    // ---- stage weights (single net; pointers pre-offset on host) ----
    {
        const float4* s4 = reinterpret_cast<const float4*>(rW3);
        float4* d4 = reinterpret_cast<float4*>(sm.W3);
        for (int x = tid; x < MID * 256 / 4; x += 256) d4[x] = s4[x];
        const float4* s2 = reinterpret_cast<const float4*>(rW2);
        float4* d2 = reinterpret_cast<float4*>(sm.W2);
        for (int x = tid; x < MID * MID / 4; x += 256) d2[x] = s2[x];
        if (tid < 3 * MID) sm.W1[tid] = rW1[tid];
        if (tid < MID) {
            sm.b1[tid]  = rb1[tid];
            sm.g1[tid]  = ln1g[tid];
            sm.bb1[tid] = ln1b[tid];
            sm.b2[tid]  = rb2[tid];
            sm.g2[tid]  = ln2g[tid];
            sm.bb2[tid] = ln2b[tid];
        }
        if (tid < 256) sm.b3[tid] = rb3[tid];
    }
    __syncthreads();

    // phase A mapping: 4 lanes per edge
    const int el = lane >> 2, sub = lane & 3;
    const int leA = w * 8 + el;          // 0..63
    const int m0 = sub * 8;

    // phase B mapping
    const int c  = tid & 63;
    const int o  = c >> 2;
    const int i0 = (c & 3) << 2;
    const int egB = tid >> 6;            // 0..3, warp-uniform

    const int ntiles = (E + 63) >> 6;
    for (int tile = blockIdx.x; tile < ntiles; tile += gridDim.x) {
        const int base = tile << 6;

        // ================= phase A =================
        {
            int ge = base + leA;
            bool valid = ge < E;
            int gec = valid ? ge : 0;
            int sn = src[gec], dn = dst[gec];

            // gather s = hprev[sn]
            *reinterpret_cast<float4*>(&sm.S[leA * NC + sub * 4]) =
                *reinterpret_cast<const float4*>(&hprev[sn * NC + sub * 4]);

            float dx = pos[dn * 3 + 0] - pos[sn * 3 + 0];
            float dy = pos[dn * 3 + 1] - pos[sn * 3 + 1];
            float dz = pos[dn * 3 + 2] - pos[sn * 3 + 2];
            float r = sqrtf(dx * dx + dy * dy + dz * dz);
            if (sub == 0) {
                sm.dstl[leA] = dn;
                if (DO_MSG1) {
                    float inv = 1.0f / fmaxf(r, 1e-8f);
                    sm.Y1[leA][0] = C1F * dy * inv;
                    sm.Y1[leA][1] = C1F * dz * inv;
                    sm.Y1[leA][2] = C1F * dx * inv;
                }
            }
            const float2 ew = reinterpret_cast<const float2*>(edge_w)[gec];
            const float f0 = ew.x, f1 = ew.y, f2 = r;

            // layer 1: h1[m] for m = m0..m0+7
            float h1v[8];
            {
                float4 ba = *reinterpret_cast<const float4*>(&sm.b1[m0]);
                float4 bb = *reinterpret_cast<const float4*>(&sm.b1[m0 + 4]);
                float4 w0a = *reinterpret_cast<const float4*>(&sm.W1[m0]);
                float4 w0b = *reinterpret_cast<const float4*>(&sm.W1[m0 + 4]);
                float4 w1a = *reinterpret_cast<const float4*>(&sm.W1[MID + m0]);
                float4 w1b = *reinterpret_cast<const float4*>(&sm.W1[MID + m0 + 4]);
                float4 w2a = *reinterpret_cast<const float4*>(&sm.W1[2 * MID + m0]);
                float4 w2b = *reinterpret_cast<const float4*>(&sm.W1[2 * MID + m0 + 4]);
                h1v[0] = fmaf(f2, w2a.x, fmaf(f1, w1a.x, fmaf(f0, w0a.x, ba.x)));
                h1v[1] = fmaf(f2, w2a.y, fmaf(f1, w1a.y, fmaf(f0, w0a.y, ba.y)));
                h1v[2] = fmaf(f2, w2a.z, fmaf(f1, w1a.z, fmaf(f0, w0a.z, ba.z)));
                h1v[3] = fmaf(f2, w2a.w, fmaf(f1, w1a.w, fmaf(f0, w0a.w, ba.w)));
                h1v[4] = fmaf(f2, w2b.x, fmaf(f1, w1b.x, fmaf(f0, w0b.x, bb.x)));
                h1v[5] = fmaf(f2, w2b.y, fmaf(f1, w1b.y, fmaf(f0, w0b.y, bb.y)));
                h1v[6] = fmaf(f2, w2b.z, fmaf(f1, w1b.z, fmaf(f0, w0b.z, bb.z)));
                h1v[7] = fmaf(f2, w2b.w, fmaf(f1, w1b.w, fmaf(f0, w0b.w, bb.w)));
            }
            // LN1 over the 4-lane group
            {
                float s = 0.f;
#pragma unroll
                for (int j = 0; j < 8; ++j) s += h1v[j];
                s += __shfl_xor_sync(FULL, s, 1);
                s += __shfl_xor_sync(FULL, s, 2);
                float mu = s * (1.0f / 32.0f);
                float v = 0.f;
#pragma unroll
                for (int j = 0; j < 8; ++j) { float cdev = h1v[j] - mu; v = fmaf(cdev, cdev, v); }
                v += __shfl_xor_sync(FULL, v, 1);
                v += __shfl_xor_sync(FULL, v, 2);
                float rs = rsqrtf(v * (1.0f / 32.0f) + 1e-5f);
                float4 ga = *reinterpret_cast<const float4*>(&sm.g1[m0]);
                float4 gb = *reinterpret_cast<const float4*>(&sm.g1[m0 + 4]);
                float4 bba = *reinterpret_cast<const float4*>(&sm.bb1[m0]);
                float4 bbb = *reinterpret_cast<const float4*>(&sm.bb1[m0 + 4]);
                const float* gv = &ga.x; const float* bv = &bba.x;
#pragma unroll
                for (int j = 0; j < 4; ++j) h1v[j] = fmaxf(fmaf((h1v[j] - mu) * rs, gv[j], bv[j]), 0.f);
                gv = &gb.x; bv = &bbb.x;
#pragma unroll
                for (int j = 0; j < 4; ++j) h1v[4 + j] = fmaxf(fmaf((h1v[4 + j] - mu) * rs, gv[j], bv[j]), 0.f);
            }
            // layer 2: h2[m] = b2[m] + sum_k h1[k] * W2[k][m]
            unsigned long long h2a[4];
            {
                ulonglong2 b2a = *reinterpret_cast<const ulonglong2*>(&sm.b2[m0]);
                ulonglong2 b2b = *reinterpret_cast<const ulonglong2*>(&sm.b2[m0 + 4]);
                h2a[0] = b2a.x; h2a[1] = b2a.y; h2a[2] = b2b.x; h2a[3] = b2b.y;
#pragma unroll
                for (int k = 0; k < MID; ++k) {
                    float hk = __shfl_sync(FULL, h1v[k & 7], (el << 2) | (k >> 3));
                    unsigned long long hd = dup2(hk);
                    ulonglong2 wA = *reinterpret_cast<const ulonglong2*>(&sm.W2[k * MID + m0]);
                    ulonglong2 wB = *reinterpret_cast<const ulonglong2*>(&sm.W2[k * MID + m0 + 4]);
                    ffma2(h2a[0], hd, wA.x);
                    ffma2(h2a[1], hd, wA.y);
                    ffma2(h2a[2], hd, wB.x);
                    ffma2(h2a[3], hd, wB.y);
                }
            }
            float h2v[8];
            unpack2(h2a[0], h2v[0], h2v[1]);
            unpack2(h2a[1], h2v[2], h2v[3]);
            unpack2(h2a[2], h2v[4], h2v[5]);
            unpack2(h2a[3], h2v[6], h2v[7]);
            // LN2 + relu
            {
                float s = 0.f;
#pragma unroll
                for (int j = 0; j < 8; ++j) s += h2v[j];
                s += __shfl_xor_sync(FULL, s, 1);
                s += __shfl_xor_sync(FULL, s, 2);
                float mu = s * (1.0f / 32.0f);
                float v = 0.f;
#pragma unroll
                for (int j = 0; j < 8; ++j) { float cdev = h2v[j] - mu; v = fmaf(cdev, cdev, v); }
                v += __shfl_xor_sync(FULL, v, 1);
                v += __shfl_xor_sync(FULL, v, 2);
                float rs = rsqrtf(v * (1.0f / 32.0f) + 1e-5f);
                float4 ga = *reinterpret_cast<const float4*>(&sm.g2[m0]);
                float4 gb = *reinterpret_cast<const float4*>(&sm.g2[m0 + 4]);
                float4 bba = *reinterpret_cast<const float4*>(&sm.bb2[m0]);
                float4 bbb = *reinterpret_cast<const float4*>(&sm.bb2[m0 + 4]);
                const float* gv = &ga.x; const float* bv = &bba.x;
#pragma unroll
                for (int j = 0; j < 4; ++j) h2v[j] = fmaxf(fmaf((h2v[j] - mu) * rs, gv[j], bv[j]), 0.f);
                gv = &gb.x; bv = &bbb.x;
#pragma unroll
                for (int j = 0; j < 4; ++j) h2v[4 + j] = fmaxf(fmaf((h2v[4 + j] - mu) * rs, gv[j], bv[j]), 0.f);
            }
            // store dup pairs {h,h}
#pragma unroll
            for (int j = 0; j < 8; ++j) {
                int m = m0 + j;
                *reinterpret_cast<float2*>(&sm.H2d[leA * 68 + 2 * m]) = make_float2(h2v[j], h2v[j]);
            }
        }
        __syncthreads();

        // ================= phase B: two passes of 8 edges =================
        const float* __restrict__ w3p = sm.W3 + c * 4;
        const float4 b3v = *reinterpret_cast<const float4*>(&sm.b3[c * 4]);
#pragma unroll
        for (int pass = 0; pass < 2; ++pass) {
            const int e0 = egB * 16 + pass * 8;
            unsigned long long acc[8][2];
#pragma unroll
            for (int j = 0; j < 8; ++j) { acc[j][0] = 0ull; acc[j][1] = 0ull; }

            const float* __restrict__ h2p = sm.H2d + e0 * 68;
#pragma unroll 4
            for (int k2 = 0; k2 < 16; ++k2) {
                ulonglong2 wk0 = *reinterpret_cast<const ulonglong2*>(&w3p[(2 * k2) * 256]);
                ulonglong2 wk1 = *reinterpret_cast<const ulonglong2*>(&w3p[(2 * k2 + 1) * 256]);
#pragma unroll
                for (int j = 0; j < 8; ++j) {
                    ulonglong2 h = *reinterpret_cast<const ulonglong2*>(&h2p[j * 68 + k2 * 4]);
                    ffma2(acc[j][0], h.x, wk0.x);
                    ffma2(acc[j][1], h.x, wk0.y);
                    ffma2(acc[j][0], h.y, wk1.x);
                    ffma2(acc[j][1], h.y, wk1.y);
                }
            }
            // epilogue
#pragma unroll
            for (int j = 0; j < 8; ++j) {
                int le = e0 + j;
                int ge = base + le;
                float a0, a1, a2, a3;
                unpack2(acc[j][0], a0, a1);
                unpack2(acc[j][1], a2, a3);
                const float4 s4 = *reinterpret_cast<const float4*>(&sm.S[le * NC + i0]);
                float t;
                t = (a0 + b3v.x) * s4.x;
                t = fmaf(a1 + b3v.y, s4.y, t);
                t = fmaf(a2 + b3v.z, s4.z, t);
                t = fmaf(a3 + b3v.w, s4.w, t);
                t += __shfl_xor_sync(FULL, t, 1);
                t += __shfl_xor_sync(FULL, t, 2);
                if ((c & 3) == 0 && ge < E) {
                    int dn = sm.dstl[le];
                    if (!DO_MSG1) {
                        atomicAdd(&accOut[dn * NC + o], Y0F * t);
                    } else {
                        float y0 = sm.Y1[le][0], y1 = sm.Y1[le][1], y2 = sm.Y1[le][2];
                        atomicAdd(&accOut[dn * NC * 3 + o * 3 + 0], t * y0);
                        atomicAdd(&accOut[dn * NC * 3 + o * 3 + 1], t * y1);
                        atomicAdd(&accOut[dn * NC * 3 + o * 3 + 2], t * y2);
                    }
                }
            }
        }
        __syncthreads();
    }
}

// ---------------- launch ----------------
extern "C" void kernel_launch(void* const* d_in, const int* in_sizes, int n_in,
                              void* d_out, int out_size) {
    const float* node_feats = (const float*)d_in[0];
    const float* pos        = (const float*)d_in[1];
    const float* edge_w     = (const float*)d_in[2];
    const float* lin1_W     = (const float*)d_in[3];
    const float* lin1_b     = (const float*)d_in[4];
    const float* lin2_W     = (const float*)d_in[5];
    const float* lin2_b     = (const float*)d_in[6];
    const float* rW1        = (const float*)d_in[7];
    const float* rb1        = (const float*)d_in[8];
    const float* ln1g       = (const float*)d_in[9];
    const float* ln1b       = (const float*)d_in[10];
    const float* rW2        = (const float*)d_in[11];
    const float* rb2        = (const float*)d_in[12];
    const float* ln2g       = (const float*)d_in[13];
    const float* ln2b       = (const float*)d_in[14];
    const float* rW3        = (const float*)d_in[15];
    const float* rb3        = (const float*)d_in[16];
    const float* Wself      = (const float*)d_in[17];
    const int*   src        = (const int*)d_in[18];
    const int*   dst        = (const int*)d_in[19];

    const int N = in_sizes[0] / F0;
    const int E = in_sizes[18];

    float *h0, *h1, *invd, *hasin, *acc0a, *acc0b, *acc1;
    int* deg;
    cudaGetSymbolAddress((void**)&h0, g_h0);
    cudaGetSymbolAddress((void**)&h1, g_h1);
    cudaGetSymbolAddress((void**)&deg, g_deg);
    cudaGetSymbolAddress((void**)&invd, g_invd);
    cudaGetSymbolAddress((void**)&hasin, g_hasin);
    cudaGetSymbolAddress((void**)&acc0a, g_acc0a);
    cudaGetSymbolAddress((void**)&acc0b, g_acc0b);
    cudaGetSymbolAddress((void**)&acc1, g_acc1);

    const size_t smemBytes = sizeof(EdgeSmem);
    cudaFuncSetAttribute(edge_kernel<false>, cudaFuncAttributeMaxDynamicSharedMemorySize, (int)smemBytes);
    cudaFuncSetAttribute(edge_kernel<true>,  cudaFuncAttributeMaxDynamicSharedMemorySize, (int)smemBytes);

    cudaMemsetAsync(deg,   0, (size_t)N * sizeof(int));
    cudaMemsetAsync(acc0a, 0, (size_t)N * NC * sizeof(float));
    cudaMemsetAsync(acc0b, 0, (size_t)N * NC * sizeof(float));
    cudaMemsetAsync(acc1,  0, (size_t)N * NC * 3 * sizeof(float));

    embed_kernel<<<(N + EMB_NODES - 1) / EMB_NODES, 256>>>(node_feats, lin1_W, lin1_b, lin2_W, lin2_b, h0, N);
    deg_kernel<<<512, 256>>>(dst, E, deg);
    invdeg_kernel<<<(N + 255) / 256, 256>>>(deg, N, invd, hasin);

    const int ntiles = (E + 63) / 64;
    int eblocks = ntiles < 444 ? ntiles : 444;

    // per-net pointer offsets
    auto net = [&](int i, const float* p, int stride) { return p + (size_t)i * stride; };

    // layer 0: net 0 (msg0 only; layer-0 msg1 is dead code in the reference)
    edge_kernel<false><<<eblocks, 256, smemBytes>>>(
        pos, edge_w, src, dst, h0,
        net(0, rW1, 3 * MID), net(0, rb1, MID), net(0, ln1g, MID), net(0, ln1b, MID),
        net(0, rW2, MID * MID), net(0, rb2, MID), net(0, ln2g, MID), net(0, ln2b, MID),
        net(0, rW3, MID * 256), net(0, rb3, 256),
        acc0a, E);
    node_update_kernel<<<(N * NC + 255) / 256, 256>>>(acc0a, invd, hasin, h0, Wself + 0 * NC * NC, h1, N);

    // layer 1: net 2 (msg0), net 3 (msg1)
    edge_kernel<false><<<eblocks, 256, smemBytes>>>(
        pos, edge_w, src, dst, h1,
        net(2, rW1, 3 * MID), net(2, rb1, MID), net(2, ln1g, MID), net(2, ln1b, MID),
        net(2, rW2, MID * MID), net(2, rb2, MID), net(2, ln2g, MID), net(2, ln2b, MID),
        net(2, rW3, MID * 256), net(2, rb3, 256),
        acc0b, E);
    edge_kernel<true><<<eblocks, 256, smemBytes>>>(
        pos, edge_w, src, dst, h1,
        net(3, rW1, 3 * MID), net(3, rb1, MID), net(3, ln1g, MID), net(3, ln1b, MID),
        net(3, rW2, MID * MID), net(3, rb2, MID), net(3, ln2g, MID), net(3, ln2b, MID),
        net(3, rW3, MID * 256), net(3, rb3, 256),
        acc1, E);

    float* out = (float*)d_out;
    node_update_kernel<<<(N * NC + 255) / 256, 256>>>(acc0b, invd, hasin, h1, Wself + 1 * NC * NC, out, N);
    out1_kernel<<<(N * NC * 3 + 255) / 256, 256>>>(acc1, invd, out + (size_t)N * NC, N);
}